// round 2
// baseline (speedup 1.0000x reference)
#include <cuda_runtime.h>

#define NB 8
#define NQ 100
#define MH 128
#define MW 128
#define OH 512
#define OW 512
#define NBLK 129                 // 4x4 output blocks per dim (shifted tiling)
#define QSTRIDE (MH*MW)

// Precomputed per-(b,q) half-weights (0.5*softmax prob for class 0/1) and per-b constants
__device__ float2 g_w[NB*NQ];
__device__ float2 g_K[NB];

__device__ __forceinline__ float tanh_fast(float x) {
    float y;
    asm("tanh.approx.f32 %0, %1;" : "=f"(y) : "f"(x));
    return y;
}

// ---------------------------------------------------------------------------
// Kernel 1: softmax over 3 class logits, keep classes 0,1, pre-scale by 0.5,
// and block-reduce the per-batch constant K_c = 0.5 * sum_q w[b,q,c].
// ---------------------------------------------------------------------------
__global__ void weights_kernel(const float* __restrict__ cls) {
    int b = blockIdx.x;
    int q = threadIdx.x;          // 0..127
    __shared__ float s0[128], s1[128];
    float hw0 = 0.f, hw1 = 0.f;
    if (q < NQ) {
        const float* p = cls + (b*NQ + q)*3;
        float l0 = p[0], l1 = p[1], l2 = p[2];
        float m  = fmaxf(l0, fmaxf(l1, l2));
        float e0 = __expf(l0 - m), e1 = __expf(l1 - m), e2 = __expf(l2 - m);
        float inv = 0.5f / (e0 + e1 + e2);
        hw0 = e0 * inv; hw1 = e1 * inv;
        g_w[b*NQ + q] = make_float2(hw0, hw1);
    }
    s0[q] = hw0; s1[q] = hw1;
    __syncthreads();
    #pragma unroll
    for (int off = 64; off > 0; off >>= 1) {
        if (q < off) { s0[q] += s0[q + off]; s1[q] += s1[q + off]; }
        __syncthreads();
    }
    if (q == 0) g_K[b] = make_float2(s0[0], s1[0]);
}

// ---------------------------------------------------------------------------
// Kernel 2: one thread = one (b, r, s) -> 4x4 output block at rows 4r-2..4r+1,
// cols 4s-2..4s+1. Uses 2x2 input stencil (rows r-1,r / cols s-1,s, clamped).
// out[b,c,y,x] = sum_q hw_c[q] * tanh(0.5 * bilerp(m_q)) + K_c[b]
// ---------------------------------------------------------------------------
__global__ void __launch_bounds__(256)
mask_kernel(const float* __restrict__ masks, float* __restrict__ out) {
    int idx = blockIdx.x * 256 + threadIdx.x;
    if (idx >= NB * NBLK * NBLK) return;

    int b   = idx / (NBLK * NBLK);
    int rem = idx - b * (NBLK * NBLK);
    int r   = rem / NBLK;
    int s   = rem - r * NBLK;

    int r0 = max(r - 1, 0), r1 = min(r, MH - 1);
    int c0 = max(s - 1, 0), c1 = min(s, MW - 1);
    int o00 = r0 * MW + c0, o01 = r0 * MW + c1;
    int o10 = r1 * MW + c0, o11 = r1 * MW + c1;

    const float*  p  = masks + (size_t)b * NQ * QSTRIDE;
    const float2* wp = g_w + b * NQ;

    float acc0[4][4], acc1[4][4];
    #pragma unroll
    for (int i = 0; i < 4; i++)
        #pragma unroll
        for (int j = 0; j < 4; j++) { acc0[i][j] = 0.f; acc1[i][j] = 0.f; }

    const float fr[4] = {0.125f, 0.375f, 0.625f, 0.875f};

    #pragma unroll 2
    for (int q = 0; q < NQ; q++, p += QSTRIDE) {
        float a  = __ldg(p + o00);
        float bb = __ldg(p + o01);
        float c  = __ldg(p + o10);
        float d  = __ldg(p + o11);
        float2 w = wp[q];

        // fold the 0.5 of sigmoid->tanh into the inputs
        float ah = 0.5f * a,  bh = 0.5f * bb;
        float ch = 0.5f * c,  dh = 0.5f * d;
        float et = bh - ah, eb = dh - ch;

        float top[4], bot[4];
        #pragma unroll
        for (int j = 0; j < 4; j++) {
            top[j] = fmaf(fr[j], et, ah);   // row r-1 horizontal lerp (halved)
            bot[j] = fmaf(fr[j], eb, ch);   // row r   horizontal lerp (halved)
        }

        #pragma unroll
        for (int j = 0; j < 4; j++) {
            float vd = bot[j] - top[j];
            #pragma unroll
            for (int i = 0; i < 4; i++) {
                float v = fmaf(fr[i], vd, top[j]);  // = 0.5 * bilinear value
                float t = tanh_fast(v);
                acc0[i][j] = fmaf(w.x, t, acc0[i][j]);
                acc1[i][j] = fmaf(w.y, t, acc1[i][j]);
            }
        }
    }

    // ---- store (predicated, float2 pairs, every output pixel written once) ----
    float2 K = g_K[b];
    int oyb = 4 * r - 2;
    int oxb = 4 * s - 2;
    bool xlo = (oxb >= 0);            // pair j=0,1
    bool xhi = (oxb + 3 < OW);        // pair j=2,3

    float* base0 = out + ((size_t)(b * 2 + 0) * OH) * OW;
    float* base1 = out + ((size_t)(b * 2 + 1) * OH) * OW;

    #pragma unroll
    for (int i = 0; i < 4; i++) {
        int oy = oyb + i;
        if ((unsigned)oy < (unsigned)OH) {
            float* r0p = base0 + (size_t)oy * OW + oxb;
            float* r1p = base1 + (size_t)oy * OW + oxb;
            if (xlo) {
                *(float2*)(r0p)     = make_float2(acc0[i][0] + K.x, acc0[i][1] + K.x);
                *(float2*)(r1p)     = make_float2(acc1[i][0] + K.y, acc1[i][1] + K.y);
            }
            if (xhi) {
                *(float2*)(r0p + 2) = make_float2(acc0[i][2] + K.x, acc0[i][3] + K.x);
                *(float2*)(r1p + 2) = make_float2(acc1[i][2] + K.y, acc1[i][3] + K.y);
            }
        }
    }
}

extern "C" void kernel_launch(void* const* d_in, const int* in_sizes, int n_in,
                              void* d_out, int out_size) {
    const float* cls   = (const float*)d_in[0];   // [8,100,3]
    const float* masks = (const float*)d_in[1];   // [8,100,128,128]
    float* out = (float*)d_out;                   // [8,2,512,512]

    weights_kernel<<<NB, 128>>>(cls);
    int total = NB * NBLK * NBLK;
    mask_kernel<<<(total + 255) / 256, 256>>>(masks, out);
}